// round 4
// baseline (speedup 1.0000x reference)
#include <cuda_runtime.h>
#include <cuda_bf16.h>
#include <cstdint>
#include <math.h>

// Problem dims
#define BB   256
#define LL   128
#define VOC  4096
#define EENC 1024
#define DDEC 1024
#define EEMB 512

// ======================= scratch (module-load allocated) ==================
// bf16 hi/lo pools (element offsets)
#define OFF_ENC   0ull
#define OFF_W1    (OFF_ENC + 33554432ull)
#define OFF_W2    (OFF_W1  + 1048576ull)
#define OFF_O2E   (OFF_W2  + 1048576ull)
#define OFF_GWI   (OFF_O2E + 2097152ull)
#define OFF_GWH   (OFF_GWI + 4718592ull)
#define OFF_F1    (OFF_GWH + 3145728ull)
#define OFF_F2    (OFF_F1  + 524288ull)
#define OFF_X     (OFF_F2  + 2097152ull)
#define OFF_HID   (OFF_X   + 1048576ull)
#define OFF_RNN   (OFF_HID + 262144ull)
#define OFF_HNEW  (OFF_RNN + 393216ull)
#define OFF_T     (OFF_HNEW+ 262144ull)
#define BF_TOTAL  (OFF_T   + 131072ull)

__device__ __nv_bfloat16 g_bh[BF_TOTAL];
__device__ __nv_bfloat16 g_bl[BF_TOTAL];

// fp32 pool
#define F_G1    0ull
#define F_RNN   (F_G1   + 262144ull)
#define F_GI    (F_RNN  + 393216ull)
#define F_GH    (F_GI   + 786432ull)
#define F_T     (F_GH   + 786432ull)
#define F_PART  (F_T    + 131072ull)
#define F_TOTAL (F_PART + 262144ull)

__device__ float g_f32[F_TOTAL];

// ======================= small helpers ====================================
__device__ __forceinline__ void cp16(uint32_t s, const void* g) {
    asm volatile("cp.async.cg.shared.global [%0], [%1], 16;"
                 :: "r"(s), "l"(__cvta_generic_to_global(g)));
}
__device__ __forceinline__ void ldm4(uint32_t* r, uint32_t addr) {
    asm volatile("ldmatrix.sync.aligned.m8n8.x4.shared.b16 {%0,%1,%2,%3}, [%4];"
        : "=r"(r[0]), "=r"(r[1]), "=r"(r[2]), "=r"(r[3]) : "r"(addr));
}
__device__ __forceinline__ void mma16816(float* c, const uint32_t* a, const uint32_t* b) {
    asm volatile("mma.sync.aligned.m16n8k16.row.col.f32.bf16.bf16.f32 "
        "{%0,%1,%2,%3}, {%4,%5,%6,%7}, {%8,%9}, {%0,%1,%2,%3};"
        : "+f"(c[0]), "+f"(c[1]), "+f"(c[2]), "+f"(c[3])
        : "r"(a[0]), "r"(a[1]), "r"(a[2]), "r"(a[3]), "r"(b[0]), "r"(b[1]));
}
__device__ __forceinline__ void do_split(const float* src, int local,
                                         unsigned long long dst) {
    float2 v = ((const float2*)src)[local];
    __nv_bfloat16 h0 = __float2bfloat16(v.x);
    __nv_bfloat16 h1 = __float2bfloat16(v.y);
    __nv_bfloat162 hp; hp.x = h0; hp.y = h1;
    __nv_bfloat162 lp;
    lp.x = __float2bfloat16(v.x - __bfloat162float(h0));
    lp.y = __float2bfloat16(v.y - __bfloat162float(h1));
    ((__nv_bfloat162*)(g_bh + dst))[local] = hp;
    ((__nv_bfloat162*)(g_bl + dst))[local] = lp;
}

// ======================= fused split kernels ==============================
// weights: W1 | W2 | o2e | gwi | gwh | f1 | f2  (float2 units)
#define WN1 524288
#define WN2 1048576
#define WN3 2097152
#define WN4 4456448
#define WN5 6029312
#define WN6 6291456
#define WN7 7340032
__global__ __launch_bounds__(256)
void split_weights(const float* __restrict__ W1, const float* __restrict__ W2,
                   const float* __restrict__ o2e, const float* __restrict__ gwi,
                   const float* __restrict__ gwh, const float* __restrict__ f1,
                   const float* __restrict__ f2)
{
    int i = blockIdx.x * blockDim.x + threadIdx.x;
    if (i < WN1)      do_split(W1,  i,       OFF_W1);
    else if (i < WN2) do_split(W2,  i - WN1, OFF_W2);
    else if (i < WN3) do_split(o2e, i - WN2, OFF_O2E);
    else if (i < WN4) do_split(gwi, i - WN3, OFF_GWI);
    else if (i < WN5) do_split(gwh, i - WN4, OFF_GWH);
    else if (i < WN6) do_split(f1,  i - WN5, OFF_F1);
    else if (i < WN7) do_split(f2,  i - WN6, OFF_F2);
}
// activations: enc | x | hidden
#define AN1 16777216
#define AN2 17301504
#define AN3 17432576
__global__ __launch_bounds__(256)
void split_acts(const float* __restrict__ enc, const float* __restrict__ x,
                const float* __restrict__ hid)
{
    int i = blockIdx.x * blockDim.x + threadIdx.x;
    if (i < AN1)      do_split(enc, i,       OFF_ENC);
    else if (i < AN2) do_split(x,   i - AN1, OFF_X);
    else if (i < AN3) do_split(hid, i - AN2, OFF_HID);
}
// single-tensor split (for intermediate activations)
__global__ __launch_bounds__(256)
void f32_split(const float* __restrict__ in, __nv_bfloat16* __restrict__ hi,
               __nv_bfloat16* __restrict__ lo, int n2)
{
    int i = blockIdx.x * blockDim.x + threadIdx.x;
    if (i >= n2) return;
    float2 v = ((const float2*)in)[i];
    __nv_bfloat16 h0 = __float2bfloat16(v.x);
    __nv_bfloat16 h1 = __float2bfloat16(v.y);
    __nv_bfloat162 hp; hp.x = h0; hp.y = h1;
    __nv_bfloat162 lp;
    lp.x = __float2bfloat16(v.x - __bfloat162float(h0));
    lp.y = __float2bfloat16(v.y - __bfloat162float(h1));
    ((__nv_bfloat162*)hi)[i] = hp;
    ((__nv_bfloat162*)lo)[i] = lp;
}

// ======================= mma.sync GEMM: C = A @ W^T =======================
// Block tile 128x128, BK=32, 8 warps (2x4), warp tile 64x32, 3-stage cp.async.
// Compensated bf16x3: D += Ah*Wh + Al*Wh + Ah*Wl   (fp32 accumulate)
enum { EPI_BIAS = 0, EPI_BIAS2 = 1, EPI_TANH = 2, EPI_SCORE = 3 };

#define ROWB     80                      // smem row stride bytes (conflict-free ldmatrix)
#define TILE_SB  (128 * ROWB)            // 10240 B per tile
#define STAGE_SB (4 * TILE_SB)           // Ah Al Wh Wl = 40960 B
#define NSTAGE   3
#define SM_PART  (NSTAGE * STAGE_SB)
#define GEMM_SMEM (SM_PART + 512 + 32)

template <int EPI>
__global__ __launch_bounds__(256, 1)
void tc_gemm(const __nv_bfloat16* __restrict__ Ah, const __nv_bfloat16* __restrict__ Al,
             const __nv_bfloat16* __restrict__ Wh, const __nv_bfloat16* __restrict__ Wl,
             int K, float* __restrict__ C, int ldc,
             const float* __restrict__ b1, const float* __restrict__ b2,
             const float* __restrict__ g1, const float* __restrict__ vw,
             float* __restrict__ partial)
{
    extern __shared__ __align__(128) char smem[];
    const uint32_t sbase = (uint32_t)__cvta_generic_to_shared(smem);
    float* part_sm = (float*)(smem + SM_PART);

    const int tid  = threadIdx.x;
    const int wid  = tid >> 5;
    const int lane = tid & 31;
    const int brow = blockIdx.y * 128;
    const int bcol = blockIdx.x * 128;
    const int m64  = (wid >> 2) * 64;
    const int n32  = (wid & 3) * 32;

    if (EPI == EPI_SCORE) {
        if (tid < 128) part_sm[tid] = 0.f;
    }

    // loader mapping: 256 threads, 2 x cp16 per tile each
    const int lrow = tid >> 1;
    const int lc0  = (tid & 1) * 2;
    const size_t aoff = (size_t)(brow + lrow) * K;
    const size_t woff = (size_t)(bcol + lrow) * K;

    auto load_stage = [&](int stage, int k0) {
        const uint32_t sb = sbase + stage * STAGE_SB + lrow * ROWB;
        const char* pAh = (const char*)(Ah + aoff + k0);
        const char* pAl = (const char*)(Al + aoff + k0);
        const char* pWh = (const char*)(Wh + woff + k0);
        const char* pWl = (const char*)(Wl + woff + k0);
        #pragma unroll
        for (int c = lc0; c < lc0 + 2; c++) {
            cp16(sb + 0 * TILE_SB + c * 16, pAh + c * 16);
            cp16(sb + 1 * TILE_SB + c * 16, pAl + c * 16);
            cp16(sb + 2 * TILE_SB + c * 16, pWh + c * 16);
            cp16(sb + 3 * TILE_SB + c * 16, pWl + c * 16);
        }
    };

    const int nk = K >> 5;

    load_stage(0, 0);
    asm volatile("cp.async.commit_group;");
    if (nk > 1) load_stage(1, 32);
    asm volatile("cp.async.commit_group;");

    float acc[4][4][4];
    #pragma unroll
    for (int i = 0; i < 4; i++)
        #pragma unroll
        for (int j = 0; j < 4; j++)
            #pragma unroll
            for (int q = 0; q < 4; q++) acc[i][j][q] = 0.f;

    const int arow_l = m64 + (lane & 7) + ((lane >> 3) & 1) * 8;
    const uint32_t akb = ((lane >> 4) & 1) * 16;
    const int nrow_l = n32 + (lane & 7) + ((lane >> 4) & 1) * 8;
    const uint32_t bkb = ((lane >> 3) & 1) * 16;

    int stage = 0;
    for (int c = 0; c < nk; c++) {
        asm volatile("cp.async.wait_group %0;" :: "n"(1));
        __syncthreads();

        // prefetch chunk c+2 into the stage freed by chunk c-1
        if (c + 2 < nk) {
            int s2 = stage + 2; if (s2 >= NSTAGE) s2 -= NSTAGE;
            load_stage(s2, (c + 2) * 32);
        }
        asm volatile("cp.async.commit_group;");

        const uint32_t sb = sbase + stage * STAGE_SB;
        #pragma unroll
        for (int kk = 0; kk < 2; kk++) {
            const uint32_t kbyte = kk * 32;
            uint32_t afh[4][4], afl[4][4], bfh[4][2], bfl[4][2];
            #pragma unroll
            for (int mt = 0; mt < 4; mt++) {
                uint32_t ra = (uint32_t)((arow_l + mt * 16) * ROWB) + akb + kbyte;
                ldm4(afh[mt], sb + 0 * TILE_SB + ra);
                ldm4(afl[mt], sb + 1 * TILE_SB + ra);
            }
            #pragma unroll
            for (int np = 0; np < 2; np++) {
                uint32_t rb = (uint32_t)((nrow_l + np * 16) * ROWB) + bkb + kbyte;
                uint32_t th[4], tl[4];
                ldm4(th, sb + 2 * TILE_SB + rb);
                ldm4(tl, sb + 3 * TILE_SB + rb);
                bfh[2 * np][0] = th[0]; bfh[2 * np][1] = th[1];
                bfh[2 * np + 1][0] = th[2]; bfh[2 * np + 1][1] = th[3];
                bfl[2 * np][0] = tl[0]; bfl[2 * np][1] = tl[1];
                bfl[2 * np + 1][0] = tl[2]; bfl[2 * np + 1][1] = tl[3];
            }
            #pragma unroll
            for (int mt = 0; mt < 4; mt++)
                #pragma unroll
                for (int nt = 0; nt < 4; nt++) {
                    mma16816(acc[mt][nt], afh[mt], bfh[nt]);
                    mma16816(acc[mt][nt], afl[mt], bfh[nt]);
                    mma16816(acc[mt][nt], afh[mt], bfl[nt]);
                }
        }
        if (++stage >= NSTAGE) stage = 0;
    }

    // ---- epilogue ----
    const int rloc0 = m64 + (lane >> 2);
    const int cloc0 = n32 + (lane & 3) * 2;

    if (EPI == EPI_SCORE) {
        const float* g1r = g1 + (size_t)blockIdx.y * 1024;
        #pragma unroll
        for (int mt = 0; mt < 4; mt++) {
            float s0 = 0.f, s1 = 0.f;
            #pragma unroll
            for (int nt = 0; nt < 4; nt++) {
                int col = bcol + cloc0 + nt * 8;
                float gw0 = g1r[col],     vw0 = vw[col];
                float gw1 = g1r[col + 1], vw1 = vw[col + 1];
                s0 += tanhf(acc[mt][nt][0] + gw0) * vw0;
                s0 += tanhf(acc[mt][nt][1] + gw1) * vw1;
                s1 += tanhf(acc[mt][nt][2] + gw0) * vw0;
                s1 += tanhf(acc[mt][nt][3] + gw1) * vw1;
            }
            atomicAdd(&part_sm[rloc0 + mt * 16], s0);
            atomicAdd(&part_sm[rloc0 + mt * 16 + 8], s1);
        }
        __syncthreads();
        if (tid < 128)
            partial[(size_t)(brow + tid) * gridDim.x + blockIdx.x] = part_sm[tid];
    } else {
        #pragma unroll
        for (int mt = 0; mt < 4; mt++) {
            const int r0 = brow + rloc0 + mt * 16;
            #pragma unroll
            for (int nt = 0; nt < 4; nt++) {
                const int col = bcol + cloc0 + nt * 8;
                float2 bb = *(const float2*)(b1 + col);
                float v0 = acc[mt][nt][0] + bb.x;
                float v1 = acc[mt][nt][1] + bb.y;
                float v2 = acc[mt][nt][2] + bb.x;
                float v3 = acc[mt][nt][3] + bb.y;
                if (EPI == EPI_BIAS2) {
                    float2 cc = *(const float2*)(b2 + col);
                    v0 += cc.x; v1 += cc.y; v2 += cc.x; v3 += cc.y;
                }
                if (EPI == EPI_TANH) {
                    v0 = tanhf(v0); v1 = tanhf(v1); v2 = tanhf(v2); v3 = tanhf(v3);
                }
                *(float2*)(C + (size_t)r0 * ldc + col)       = make_float2(v0, v1);
                *(float2*)(C + (size_t)(r0 + 8) * ldc + col) = make_float2(v2, v3);
            }
        }
    }
}

// ============== softmax + context (one block per batch element) ===========
__global__ __launch_bounds__(256)
void attn_softmax_context(const float* __restrict__ part, int npart,
                          const float* __restrict__ enc,
                          const float* __restrict__ Vb,
                          float* __restrict__ attn_out,
                          float* __restrict__ rnn)
{
    const int b   = blockIdx.x;
    const int tid = threadIdx.x;
    __shared__ float logit[LL];

    if (tid < LL) {
        const float* pr = part + (size_t)(b * LL + tid) * npart;
        float s = Vb[0];
        for (int j = 0; j < npart; j++) s += pr[j];
        logit[tid] = s;
    }
    __syncthreads();

    if (tid < 32) {
        const int lane = tid;
        float m = -1e30f;
        for (int l = lane; l < LL; l += 32) m = fmaxf(m, logit[l]);
        #pragma unroll
        for (int o = 16; o; o >>= 1) m = fmaxf(m, __shfl_xor_sync(0xffffffffu, m, o));
        float s = 0.f;
        for (int l = lane; l < LL; l += 32) {
            float e = expf(logit[l] - m);
            logit[l] = e;
            s += e;
        }
        #pragma unroll
        for (int o = 16; o; o >>= 1) s += __shfl_xor_sync(0xffffffffu, s, o);
        float inv = 1.f / s;
        for (int l = lane; l < LL; l += 32) logit[l] *= inv;
    }
    __syncthreads();

    if (tid < LL) attn_out[b * LL + tid] = logit[tid];

    float4 acc = make_float4(0.f, 0.f, 0.f, 0.f);
    const float* encb = enc + (size_t)b * LL * EENC;
    const int e4 = tid * 4;
    #pragma unroll 4
    for (int l = 0; l < LL; l++) {
        float a = logit[l];
        float4 v = *(const float4*)(encb + (size_t)l * EENC + e4);
        acc.x += a * v.x; acc.y += a * v.y; acc.z += a * v.z; acc.w += a * v.w;
    }
    *(float4*)(rnn + (size_t)b * 1536 + e4) = acc;
}

// ============================ GRU gates ===================================
__global__ __launch_bounds__(256)
void gru_gate(const float* __restrict__ gi, const float* __restrict__ gh,
              const float* __restrict__ h0, float* __restrict__ hnew)
{
    const int idx = blockIdx.x * blockDim.x + threadIdx.x;
    const int b = idx >> 10;
    const int d = idx & 1023;
    const float* gib = gi + (size_t)b * 3072;
    const float* ghb = gh + (size_t)b * 3072;
    float r = 1.f / (1.f + expf(-(gib[d] + ghb[d])));
    float z = 1.f / (1.f + expf(-(gib[1024 + d] + ghb[1024 + d])));
    float n = tanhf(gib[2048 + d] + r * ghb[2048 + d]);
    hnew[idx] = (1.f - z) * n + z * h0[idx];
}

// ============================ launch ======================================
extern "C" void kernel_launch(void* const* d_in, const int* in_sizes, int n_in,
                              void* d_out, int out_size)
{
    (void)in_sizes; (void)n_in; (void)out_size;

    const float* x      = (const float*)d_in[0];
    const float* hidden = (const float*)d_in[1];
    const float* enc    = (const float*)d_in[2];
    const float* W1_w   = (const float*)d_in[3];
    const float* W1_b   = (const float*)d_in[4];
    const float* W2_w   = (const float*)d_in[5];
    const float* W2_b   = (const float*)d_in[6];
    const float* V_w    = (const float*)d_in[7];
    const float* V_b    = (const float*)d_in[8];
    const float* o2e_w  = (const float*)d_in[9];
    const float* o2e_b  = (const float*)d_in[10];
    const float* gwi    = (const float*)d_in[11];
    const float* gwh    = (const float*)d_in[12];
    const float* gbi    = (const float*)d_in[13];
    const float* gbh    = (const float*)d_in[14];
    const float* f1w    = (const float*)d_in[15];
    const float* f1b    = (const float*)d_in[16];
    const float* f2w    = (const float*)d_in[17];
    const float* f2b    = (const float*)d_in[18];

    float* out  = (float*)d_out;
    float* hnew = out + (size_t)BB * VOC;
    float* attn = hnew + (size_t)BB * DDEC;

    __nv_bfloat16* bh = nullptr;
    __nv_bfloat16* bl = nullptr;
    float* fs = nullptr;
    cudaGetSymbolAddress((void**)&bh, g_bh);
    cudaGetSymbolAddress((void**)&bl, g_bl);
    cudaGetSymbolAddress((void**)&fs, g_f32);

    float* g1   = fs + F_G1;
    float* rnn  = fs + F_RNN;
    float* gi   = fs + F_GI;
    float* gh   = fs + F_GH;
    float* tbuf = fs + F_T;
    float* part = fs + F_PART;

    cudaFuncSetAttribute(tc_gemm<EPI_BIAS>,  cudaFuncAttributeMaxDynamicSharedMemorySize, GEMM_SMEM);
    cudaFuncSetAttribute(tc_gemm<EPI_BIAS2>, cudaFuncAttributeMaxDynamicSharedMemorySize, GEMM_SMEM);
    cudaFuncSetAttribute(tc_gemm<EPI_TANH>,  cudaFuncAttributeMaxDynamicSharedMemorySize, GEMM_SMEM);
    cudaFuncSetAttribute(tc_gemm<EPI_SCORE>, cudaFuncAttributeMaxDynamicSharedMemorySize, GEMM_SMEM);

    dim3 blk(256);

    // 0) weight splits (one fused launch)
    split_weights<<<WN7 / 256, 256>>>(W1_w, W2_w, o2e_w, gwi, gwh, f1w, f2w);
    // 1) activation splits (one fused launch)
    split_acts<<<AN3 / 256, 256>>>(enc, x, hidden);

    // 2) g1 = h0 @ W2^T + W2_b + W1_b                 (256 x 1024, K=1024)
    tc_gemm<EPI_BIAS2><<<dim3(8, 2), blk, GEMM_SMEM>>>(
        bh + OFF_HID, bl + OFF_HID, bh + OFF_W2, bl + OFF_W2,
        1024, g1, 1024, W2_b, W1_b, nullptr, nullptr, nullptr);

    // 3) x_emb = x @ out2emb^T + b -> rnn[:, 1024:1536] (256 x 512, K=4096)
    tc_gemm<EPI_BIAS><<<dim3(4, 2), blk, GEMM_SMEM>>>(
        bh + OFF_X, bl + OFF_X, bh + OFF_O2E, bl + OFF_O2E,
        4096, rnn + 1024, 1536, o2e_b, nullptr, nullptr, nullptr, nullptr);

    // 4) gh = h0 @ gru_wh^T + gru_bh                  (256 x 3072, K=1024)
    tc_gemm<EPI_BIAS><<<dim3(24, 2), blk, GEMM_SMEM>>>(
        bh + OFF_HID, bl + OFF_HID, bh + OFF_GWH, bl + OFF_GWH,
        1024, gh, 3072, gbh, nullptr, nullptr, nullptr, nullptr);

    // 5) score GEMM partial logits (launch index 5 -> profiled by ncu -s 5)
    tc_gemm<EPI_SCORE><<<dim3(8, 256), blk, GEMM_SMEM>>>(
        bh + OFF_ENC, bl + OFF_ENC, bh + OFF_W1, bl + OFF_W1,
        1024, nullptr, 0, nullptr, nullptr, g1, V_w, part);

    // 6) softmax + attn out + context -> rnn[:, 0:1024]
    attn_softmax_context<<<BB, 256>>>(part, 8, enc, V_b, attn, rnn);

    // 7) rnn -> bf16
    f32_split<<<(393216 / 2 + 255) / 256, 256>>>(rnn, bh + OFF_RNN, bl + OFF_RNN, 393216 / 2);

    // 8) gi = rnn_in @ gru_wi^T + gru_bi              (256 x 3072, K=1536)
    tc_gemm<EPI_BIAS><<<dim3(24, 2), blk, GEMM_SMEM>>>(
        bh + OFF_RNN, bl + OFF_RNN, bh + OFF_GWI, bl + OFF_GWI,
        1536, gi, 3072, gbi, nullptr, nullptr, nullptr, nullptr);

    // 9) GRU gates -> h_new (output)
    gru_gate<<<(BB * DDEC) / 256, 256>>>(gi, gh, hidden, hnew);

    // 10) h_new -> bf16
    f32_split<<<(262144 / 2 + 255) / 256, 256>>>(hnew, bh + OFF_HNEW, bl + OFF_HNEW, 262144 / 2);

    // 11) t = tanh(h_new @ fc1^T + fc1_b)             (256 x 512, K=1024)
    tc_gemm<EPI_TANH><<<dim3(4, 2), blk, GEMM_SMEM>>>(
        bh + OFF_HNEW, bl + OFF_HNEW, bh + OFF_F1, bl + OFF_F1,
        1024, tbuf, 512, f1b, nullptr, nullptr, nullptr, nullptr);

    // 12) t -> bf16
    f32_split<<<(131072 / 2 + 255) / 256, 256>>>(tbuf, bh + OFF_T, bl + OFF_T, 131072 / 2);

    // 13) out = t @ fc2^T + fc2_b                     (256 x 4096, K=512)
    tc_gemm<EPI_BIAS><<<dim3(32, 2), blk, GEMM_SMEM>>>(
        bh + OFF_T, bl + OFF_T, bh + OFF_F2, bl + OFF_F2,
        512, out, 4096, f2b, nullptr, nullptr, nullptr, nullptr);
}

// round 5
// speedup vs baseline: 1.4470x; 1.4470x over previous
#include <cuda_runtime.h>
#include <cuda_bf16.h>
#include <cstdint>
#include <math.h>

// Problem dims
#define BB   256
#define LL   128
#define VOC  4096
#define EENC 1024
#define DDEC 1024
#define EEMB 512

// ======================= scratch (module-load allocated) ==================
// bf16 hi/lo pools (element offsets)
#define OFF_ENC   0ull
#define OFF_W1    (OFF_ENC + 33554432ull)
#define OFF_W2    (OFF_W1  + 1048576ull)
#define OFF_O2E   (OFF_W2  + 1048576ull)
#define OFF_GWI   (OFF_O2E + 2097152ull)
#define OFF_GWH   (OFF_GWI + 4718592ull)
#define OFF_F1    (OFF_GWH + 3145728ull)
#define OFF_F2    (OFF_F1  + 524288ull)
#define OFF_X     (OFF_F2  + 2097152ull)
#define OFF_HID   (OFF_X   + 1048576ull)
#define OFF_RNN   (OFF_HID + 262144ull)
#define OFF_HNEW  (OFF_RNN + 393216ull)
#define OFF_T     (OFF_HNEW+ 262144ull)
#define BF_TOTAL  (OFF_T   + 131072ull)

__device__ __nv_bfloat16 g_bh[BF_TOTAL];
__device__ __nv_bfloat16 g_bl[BF_TOTAL];

// fp32 pool
#define F_G1    0ull
#define F_RNN   (F_G1   + 262144ull)
#define F_GI    (F_RNN  + 393216ull)
#define F_GH    (F_GI   + 786432ull)
#define F_T     (F_GH   + 786432ull)
#define F_PART  (F_T    + 131072ull)
#define F_TOTAL (F_PART + 524288ull)      // 32768 rows x 16 partials

__device__ float g_f32[F_TOTAL];

// ======================= small helpers ====================================
__device__ __forceinline__ void cp16(uint32_t s, const void* g) {
    asm volatile("cp.async.cg.shared.global [%0], [%1], 16;"
                 :: "r"(s), "l"(__cvta_generic_to_global(g)));
}
__device__ __forceinline__ void ldm4(uint32_t* r, uint32_t addr) {
    asm volatile("ldmatrix.sync.aligned.m8n8.x4.shared.b16 {%0,%1,%2,%3}, [%4];"
        : "=r"(r[0]), "=r"(r[1]), "=r"(r[2]), "=r"(r[3]) : "r"(addr));
}
__device__ __forceinline__ void mma16816(float* c, const uint32_t* a, const uint32_t* b) {
    asm volatile("mma.sync.aligned.m16n8k16.row.col.f32.bf16.bf16.f32 "
        "{%0,%1,%2,%3}, {%4,%5,%6,%7}, {%8,%9}, {%0,%1,%2,%3};"
        : "+f"(c[0]), "+f"(c[1]), "+f"(c[2]), "+f"(c[3])
        : "r"(a[0]), "r"(a[1]), "r"(a[2]), "r"(a[3]), "r"(b[0]), "r"(b[1]));
}
__device__ __forceinline__ void do_split(const float* src, int local,
                                         unsigned long long dst) {
    float2 v = ((const float2*)src)[local];
    __nv_bfloat16 h0 = __float2bfloat16(v.x);
    __nv_bfloat16 h1 = __float2bfloat16(v.y);
    __nv_bfloat162 hp; hp.x = h0; hp.y = h1;
    __nv_bfloat162 lp;
    lp.x = __float2bfloat16(v.x - __bfloat162float(h0));
    lp.y = __float2bfloat16(v.y - __bfloat162float(h1));
    ((__nv_bfloat162*)(g_bh + dst))[local] = hp;
    ((__nv_bfloat162*)(g_bl + dst))[local] = lp;
}

// ======================= fused split kernels ==============================
#define WN1 524288
#define WN2 1048576
#define WN3 2097152
#define WN4 4456448
#define WN5 6029312
#define WN6 6291456
#define WN7 7340032
__global__ __launch_bounds__(256)
void split_weights(const float* __restrict__ W1, const float* __restrict__ W2,
                   const float* __restrict__ o2e, const float* __restrict__ gwi,
                   const float* __restrict__ gwh, const float* __restrict__ f1,
                   const float* __restrict__ f2)
{
    int i = blockIdx.x * blockDim.x + threadIdx.x;
    if (i < WN1)      do_split(W1,  i,       OFF_W1);
    else if (i < WN2) do_split(W2,  i - WN1, OFF_W2);
    else if (i < WN3) do_split(o2e, i - WN2, OFF_O2E);
    else if (i < WN4) do_split(gwi, i - WN3, OFF_GWI);
    else if (i < WN5) do_split(gwh, i - WN4, OFF_GWH);
    else if (i < WN6) do_split(f1,  i - WN5, OFF_F1);
    else if (i < WN7) do_split(f2,  i - WN6, OFF_F2);
}
#define AN1 16777216
#define AN2 17301504
#define AN3 17432576
__global__ __launch_bounds__(256)
void split_acts(const float* __restrict__ enc, const float* __restrict__ x,
                const float* __restrict__ hid)
{
    int i = blockIdx.x * blockDim.x + threadIdx.x;
    if (i < AN1)      do_split(enc, i,       OFF_ENC);
    else if (i < AN2) do_split(x,   i - AN1, OFF_X);
    else if (i < AN3) do_split(hid, i - AN2, OFF_HID);
}
__global__ __launch_bounds__(256)
void f32_split(const float* __restrict__ in, __nv_bfloat16* __restrict__ hi,
               __nv_bfloat16* __restrict__ lo, int n2)
{
    int i = blockIdx.x * blockDim.x + threadIdx.x;
    if (i >= n2) return;
    float2 v = ((const float2*)in)[i];
    __nv_bfloat16 h0 = __float2bfloat16(v.x);
    __nv_bfloat16 h1 = __float2bfloat16(v.y);
    __nv_bfloat162 hp; hp.x = h0; hp.y = h1;
    __nv_bfloat162 lp;
    lp.x = __float2bfloat16(v.x - __bfloat162float(h0));
    lp.y = __float2bfloat16(v.y - __bfloat162float(h1));
    ((__nv_bfloat162*)hi)[i] = hp;
    ((__nv_bfloat162*)lo)[i] = lp;
}
// split with tanh pre-applied (for fc1 output)
__global__ __launch_bounds__(256)
void f32_split_tanh(const float* __restrict__ in, __nv_bfloat16* __restrict__ hi,
                    __nv_bfloat16* __restrict__ lo, int n2)
{
    int i = blockIdx.x * blockDim.x + threadIdx.x;
    if (i >= n2) return;
    float2 v = ((const float2*)in)[i];
    v.x = tanhf(v.x); v.y = tanhf(v.y);
    __nv_bfloat16 h0 = __float2bfloat16(v.x);
    __nv_bfloat16 h1 = __float2bfloat16(v.y);
    __nv_bfloat162 hp; hp.x = h0; hp.y = h1;
    __nv_bfloat162 lp;
    lp.x = __float2bfloat16(v.x - __bfloat162float(h0));
    lp.y = __float2bfloat16(v.y - __bfloat162float(h1));
    ((__nv_bfloat162*)hi)[i] = hp;
    ((__nv_bfloat162*)lo)[i] = lp;
}

// ================= bias pre-init (resets ALL atomic targets every call) ===
// regions: g1(256x1024: W1b+W2b) | rnn_xemb(256x512) | gi(256x3072) |
//          gh(256x3072) | tbuf(256x512) | out(256x4096)
__global__ __launch_bounds__(256)
void bias_init(float* __restrict__ g1, float* __restrict__ rnn,
               float* __restrict__ gi, float* __restrict__ gh,
               float* __restrict__ tbuf, float* __restrict__ out,
               const float* __restrict__ w1b, const float* __restrict__ w2b,
               const float* __restrict__ o2eb, const float* __restrict__ gbi,
               const float* __restrict__ gbh, const float* __restrict__ f1b,
               const float* __restrict__ f2b)
{
    int i = blockIdx.x * blockDim.x + threadIdx.x;
    if (i < 262144) {
        g1[i] = w1b[i & 1023] + w2b[i & 1023];
    } else if (i < 393216) {
        int j = i - 262144;
        rnn[(j >> 9) * 1536 + 1024 + (j & 511)] = o2eb[j & 511];
    } else if (i < 1179648) {
        int j = i - 393216;
        gi[j] = gbi[j % 3072];
    } else if (i < 1966080) {
        int j = i - 1179648;
        gh[j] = gbh[j % 3072];
    } else if (i < 2097152) {
        int j = i - 1966080;
        tbuf[j] = f1b[j & 511];
    } else {
        int j = i - 2097152;
        out[j] = f2b[j & 4095];
    }
}
#define BIAS_TOTAL 3145728

// ======================= split-K mma GEMM: C (+)= A @ W^T ================
// Block tile 128(M) x 64(N), BK=32, 2 stages, 8 warps (4m x 2n), warp 32x32.
// Compensated bf16x3: D += Ah*Wh + Al*Wh + Ah*Wl, fp32 accumulate.
// EPI_ATOMIC: atomicAdd into bias-preinitialized C (split-K over blockIdx.z).
// EPI_SCORE : weighted-tanh row partials -> partial[row*16 + bx].
enum { EPI_ATOMIC = 0, EPI_SCORE = 1 };

#define ROWB      80
#define TILE_A_SB (128 * ROWB)           // 10240
#define TILE_W_SB (64 * ROWB)            // 5120
#define STAGE_SB  (2 * TILE_A_SB + 2 * TILE_W_SB)   // 30720
#define NSTAGE    2
#define SM_PART   (NSTAGE * STAGE_SB)    // 61440
#define GEMM_SMEM (SM_PART + 512 + 32)

template <int EPI>
__global__ __launch_bounds__(256, 2)
void gemm64(const __nv_bfloat16* __restrict__ Ah, const __nv_bfloat16* __restrict__ Al,
            const __nv_bfloat16* __restrict__ Wh, const __nv_bfloat16* __restrict__ Wl,
            int K, int Kchunk, float* __restrict__ C, int ldc,
            const float* __restrict__ g1, const float* __restrict__ vw,
            float* __restrict__ partial)
{
    extern __shared__ __align__(128) char smem[];
    const uint32_t sbase = (uint32_t)__cvta_generic_to_shared(smem);
    float* part_sm = (float*)(smem + SM_PART);

    const int tid  = threadIdx.x;
    const int wid  = tid >> 5;
    const int lane = tid & 31;
    const int brow = blockIdx.y * 128;
    const int bcol = blockIdx.x * 64;
    const int k0   = blockIdx.z * Kchunk;
    const int m32  = (wid >> 1) * 32;
    const int n32w = (wid & 1) * 32;

    if (EPI == EPI_SCORE) {
        if (tid < 128) part_sm[tid] = 0.f;
    }

    // loader mapping
    const int lrA = tid >> 1;            // 0..127
    const int cA  = (tid & 1) * 2;       // 16B chunk base
    const int lrW = tid >> 2;            // 0..63
    const int cW  = tid & 3;
    const size_t aoff = (size_t)(brow + lrA) * K + k0;
    const size_t woff = (size_t)(bcol + lrW) * K + k0;

    auto load_stage = [&](int stage, int kk0) {
        const uint32_t sA = sbase + stage * STAGE_SB + lrA * ROWB;
        const uint32_t sW = sbase + stage * STAGE_SB + 2 * TILE_A_SB + lrW * ROWB;
        const char* pAh = (const char*)(Ah + aoff + kk0);
        const char* pAl = (const char*)(Al + aoff + kk0);
        const char* pWh = (const char*)(Wh + woff + kk0);
        const char* pWl = (const char*)(Wl + woff + kk0);
        #pragma unroll
        for (int c = cA; c < cA + 2; c++) {
            cp16(sA + c * 16, pAh + c * 16);
            cp16(sA + TILE_A_SB + c * 16, pAl + c * 16);
        }
        cp16(sW + cW * 16, pWh + cW * 16);
        cp16(sW + TILE_W_SB + cW * 16, pWl + cW * 16);
    };

    const int nk = Kchunk >> 5;

    load_stage(0, 0);
    asm volatile("cp.async.commit_group;");
    if (nk > 1) load_stage(1, 32);
    asm volatile("cp.async.commit_group;");

    float acc[2][4][4];
    #pragma unroll
    for (int i = 0; i < 2; i++)
        #pragma unroll
        for (int j = 0; j < 4; j++)
            #pragma unroll
            for (int q = 0; q < 4; q++) acc[i][j][q] = 0.f;

    const int arow_l = m32 + (lane & 15);
    const uint32_t akb = ((lane >> 4) & 1) * 16;
    const int nrow_l = n32w + (lane & 7) + ((lane >> 4) & 1) * 8;
    const uint32_t bkb = ((lane >> 3) & 1) * 16;

    for (int c = 0; c < nk; c++) {
        asm volatile("cp.async.wait_group %0;" :: "n"(1));
        __syncthreads();

        const uint32_t sb = sbase + (c & 1) * STAGE_SB;
        #pragma unroll
        for (int kk = 0; kk < 2; kk++) {
            const uint32_t kbyte = kk * 32;
            uint32_t afh[2][4], afl[2][4], bfh[4][2], bfl[4][2];
            #pragma unroll
            for (int mt = 0; mt < 2; mt++) {
                uint32_t ra = (uint32_t)((arow_l + mt * 16) * ROWB) + akb + kbyte;
                ldm4(afh[mt], sb + ra);
                ldm4(afl[mt], sb + TILE_A_SB + ra);
            }
            #pragma unroll
            for (int np = 0; np < 2; np++) {
                uint32_t rb = (uint32_t)((nrow_l + np * 16) * ROWB) + bkb + kbyte;
                uint32_t th[4], tl[4];
                ldm4(th, sb + 2 * TILE_A_SB + rb);
                ldm4(tl, sb + 2 * TILE_A_SB + TILE_W_SB + rb);
                bfh[2 * np][0] = th[0]; bfh[2 * np][1] = th[1];
                bfh[2 * np + 1][0] = th[2]; bfh[2 * np + 1][1] = th[3];
                bfl[2 * np][0] = tl[0]; bfl[2 * np][1] = tl[1];
                bfl[2 * np + 1][0] = tl[2]; bfl[2 * np + 1][1] = tl[3];
            }
            #pragma unroll
            for (int mt = 0; mt < 2; mt++)
                #pragma unroll
                for (int nt = 0; nt < 4; nt++) {
                    mma16816(acc[mt][nt], afh[mt], bfh[nt]);
                    mma16816(acc[mt][nt], afl[mt], bfh[nt]);
                    mma16816(acc[mt][nt], afh[mt], bfl[nt]);
                }
        }
        __syncthreads();

        if (c + 2 < nk) load_stage(c & 1, (c + 2) * 32);
        asm volatile("cp.async.commit_group;");
    }

    // ---- epilogue ----
    const int rloc0 = m32 + (lane >> 2);         // + mt*16, + 8 for upper half
    const int cloc0 = n32w + (lane & 3) * 2;     // + nt*8

    if (EPI == EPI_SCORE) {
        const float* g1r = g1 + (size_t)blockIdx.y * 1024;
        #pragma unroll
        for (int mt = 0; mt < 2; mt++) {
            float s0 = 0.f, s1 = 0.f;
            #pragma unroll
            for (int nt = 0; nt < 4; nt++) {
                int col = bcol + cloc0 + nt * 8;
                float gw0 = g1r[col],     vw0 = vw[col];
                float gw1 = g1r[col + 1], vw1 = vw[col + 1];
                s0 += tanhf(acc[mt][nt][0] + gw0) * vw0;
                s0 += tanhf(acc[mt][nt][1] + gw1) * vw1;
                s1 += tanhf(acc[mt][nt][2] + gw0) * vw0;
                s1 += tanhf(acc[mt][nt][3] + gw1) * vw1;
            }
            atomicAdd(&part_sm[rloc0 + mt * 16], s0);
            atomicAdd(&part_sm[rloc0 + mt * 16 + 8], s1);
        }
        __syncthreads();
        if (tid < 128)
            partial[(size_t)(brow + tid) * gridDim.x + blockIdx.x] = part_sm[tid];
    } else {
        #pragma unroll
        for (int mt = 0; mt < 2; mt++) {
            const int r0 = brow + rloc0 + mt * 16;
            #pragma unroll
            for (int nt = 0; nt < 4; nt++) {
                const int col = bcol + cloc0 + nt * 8;
                float* c0 = C + (size_t)r0 * ldc + col;
                float* c1 = C + (size_t)(r0 + 8) * ldc + col;
                atomicAdd(c0,     acc[mt][nt][0]);
                atomicAdd(c0 + 1, acc[mt][nt][1]);
                atomicAdd(c1,     acc[mt][nt][2]);
                atomicAdd(c1 + 1, acc[mt][nt][3]);
            }
        }
    }
}

// ============== softmax + context (one block per batch element) ===========
__global__ __launch_bounds__(256)
void attn_softmax_context(const float* __restrict__ part, int npart,
                          const float* __restrict__ enc,
                          const float* __restrict__ Vb,
                          float* __restrict__ attn_out,
                          float* __restrict__ rnn)
{
    const int b   = blockIdx.x;
    const int tid = threadIdx.x;
    __shared__ float logit[LL];

    if (tid < LL) {
        const float* pr = part + (size_t)(b * LL + tid) * npart;
        float s = Vb[0];
        for (int j = 0; j < npart; j++) s += pr[j];
        logit[tid] = s;
    }
    __syncthreads();

    if (tid < 32) {
        const int lane = tid;
        float m = -1e30f;
        for (int l = lane; l < LL; l += 32) m = fmaxf(m, logit[l]);
        #pragma unroll
        for (int o = 16; o; o >>= 1) m = fmaxf(m, __shfl_xor_sync(0xffffffffu, m, o));
        float s = 0.f;
        for (int l = lane; l < LL; l += 32) {
            float e = expf(logit[l] - m);
            logit[l] = e;
            s += e;
        }
        #pragma unroll
        for (int o = 16; o; o >>= 1) s += __shfl_xor_sync(0xffffffffu, s, o);
        float inv = 1.f / s;
        for (int l = lane; l < LL; l += 32) logit[l] *= inv;
    }
    __syncthreads();

    if (tid < LL) attn_out[b * LL + tid] = logit[tid];

    float4 acc = make_float4(0.f, 0.f, 0.f, 0.f);
    const float* encb = enc + (size_t)b * LL * EENC;
    const int e4 = tid * 4;
    #pragma unroll 4
    for (int l = 0; l < LL; l++) {
        float a = logit[l];
        float4 v = *(const float4*)(encb + (size_t)l * EENC + e4);
        acc.x += a * v.x; acc.y += a * v.y; acc.z += a * v.z; acc.w += a * v.w;
    }
    *(float4*)(rnn + (size_t)b * 1536 + e4) = acc;
}

// ============================ GRU gates ===================================
__global__ __launch_bounds__(256)
void gru_gate(const float* __restrict__ gi, const float* __restrict__ gh,
              const float* __restrict__ h0, float* __restrict__ hnew)
{
    const int idx = blockIdx.x * blockDim.x + threadIdx.x;
    const int b = idx >> 10;
    const int d = idx & 1023;
    const float* gib = gi + (size_t)b * 3072;
    const float* ghb = gh + (size_t)b * 3072;
    float r = 1.f / (1.f + expf(-(gib[d] + ghb[d])));
    float z = 1.f / (1.f + expf(-(gib[1024 + d] + ghb[1024 + d])));
    float n = tanhf(gib[2048 + d] + r * ghb[2048 + d]);
    hnew[idx] = (1.f - z) * n + z * h0[idx];
}

// ============================ launch ======================================
extern "C" void kernel_launch(void* const* d_in, const int* in_sizes, int n_in,
                              void* d_out, int out_size)
{
    (void)in_sizes; (void)n_in; (void)out_size;

    const float* x      = (const float*)d_in[0];
    const float* hidden = (const float*)d_in[1];
    const float* enc    = (const float*)d_in[2];
    const float* W1_w   = (const float*)d_in[3];
    const float* W1_b   = (const float*)d_in[4];
    const float* W2_w   = (const float*)d_in[5];
    const float* W2_b   = (const float*)d_in[6];
    const float* V_w    = (const float*)d_in[7];
    const float* V_b    = (const float*)d_in[8];
    const float* o2e_w  = (const float*)d_in[9];
    const float* o2e_b  = (const float*)d_in[10];
    const float* gwi    = (const float*)d_in[11];
    const float* gwh    = (const float*)d_in[12];
    const float* gbi    = (const float*)d_in[13];
    const float* gbh    = (const float*)d_in[14];
    const float* f1w    = (const float*)d_in[15];
    const float* f1b    = (const float*)d_in[16];
    const float* f2w    = (const float*)d_in[17];
    const float* f2b    = (const float*)d_in[18];

    float* out  = (float*)d_out;
    float* hnew = out + (size_t)BB * VOC;
    float* attn = hnew + (size_t)BB * DDEC;

    __nv_bfloat16* bh = nullptr;
    __nv_bfloat16* bl = nullptr;
    float* fs = nullptr;
    cudaGetSymbolAddress((void**)&bh, g_bh);
    cudaGetSymbolAddress((void**)&bl, g_bl);
    cudaGetSymbolAddress((void**)&fs, g_f32);

    float* g1   = fs + F_G1;
    float* rnn  = fs + F_RNN;
    float* gi   = fs + F_GI;
    float* gh   = fs + F_GH;
    float* tbuf = fs + F_T;
    float* part = fs + F_PART;

    cudaFuncSetAttribute(gemm64<EPI_ATOMIC>, cudaFuncAttributeMaxDynamicSharedMemorySize, GEMM_SMEM);
    cudaFuncSetAttribute(gemm64<EPI_SCORE>,  cudaFuncAttributeMaxDynamicSharedMemorySize, GEMM_SMEM);

    dim3 blk(256);

    // 0) weight splits
    split_weights<<<WN7 / 256, 256>>>(W1_w, W2_w, o2e_w, gwi, gwh, f1w, f2w);
    // 1) activation splits
    split_acts<<<AN3 / 256, 256>>>(enc, x, hidden);
    // 2) bias preinit (resets every atomic target each call -> graph safe)
    bias_init<<<BIAS_TOTAL / 256, 256>>>(g1, rnn, gi, gh, tbuf, out,
                                         W1_b, W2_b, o2e_b, gbi, gbh, f1b, f2b);

    // 3) g1 += h0 @ W2^T            (256x1024, K=1024, splitK=4)  [ncu captures this]
    gemm64<EPI_ATOMIC><<<dim3(16, 2, 4), blk, GEMM_SMEM>>>(
        bh + OFF_HID, bl + OFF_HID, bh + OFF_W2, bl + OFF_W2,
        1024, 256, g1, 1024, nullptr, nullptr, nullptr);

    // 4) score GEMM -> weighted-tanh row partials   (32768x1024, K=1024)
    gemm64<EPI_SCORE><<<dim3(16, 256, 1), blk, GEMM_SMEM>>>(
        bh + OFF_ENC, bl + OFF_ENC, bh + OFF_W1, bl + OFF_W1,
        1024, 1024, nullptr, 0, g1, V_w, part);

    // 5) softmax + attn out + context -> rnn[:, 0:1024]
    attn_softmax_context<<<BB, 256>>>(part, 16, enc, V_b, attn, rnn);

    // 6) x_emb += x @ out2emb^T     (256x512, K=4096, splitK=8) -> rnn[:,1024:]
    gemm64<EPI_ATOMIC><<<dim3(8, 2, 8), blk, GEMM_SMEM>>>(
        bh + OFF_X, bl + OFF_X, bh + OFF_O2E, bl + OFF_O2E,
        4096, 512, rnn + 1024, 1536, nullptr, nullptr, nullptr);

    // 7) gh += h0 @ gru_wh^T        (256x3072, K=1024, splitK=2)
    gemm64<EPI_ATOMIC><<<dim3(48, 2, 2), blk, GEMM_SMEM>>>(
        bh + OFF_HID, bl + OFF_HID, bh + OFF_GWH, bl + OFF_GWH,
        1024, 512, gh, 3072, nullptr, nullptr, nullptr);

    // 8) rnn -> bf16
    f32_split<<<(393216 / 2) / 256, 256>>>(rnn, bh + OFF_RNN, bl + OFF_RNN, 393216 / 2);

    // 9) gi += rnn_in @ gru_wi^T    (256x3072, K=1536, splitK=2)
    gemm64<EPI_ATOMIC><<<dim3(48, 2, 2), blk, GEMM_SMEM>>>(
        bh + OFF_RNN, bl + OFF_RNN, bh + OFF_GWI, bl + OFF_GWI,
        1536, 768, gi, 3072, nullptr, nullptr, nullptr);

    // 10) GRU gates -> h_new (output)
    gru_gate<<<(BB * DDEC) / 256, 256>>>(gi, gh, hidden, hnew);

    // 11) h_new -> bf16
    f32_split<<<(262144 / 2) / 256, 256>>>(hnew, bh + OFF_HNEW, bl + OFF_HNEW, 262144 / 2);

    // 12) tbuf += h_new @ fc1^T     (256x512, K=1024, splitK=8)
    gemm64<EPI_ATOMIC><<<dim3(8, 2, 8), blk, GEMM_SMEM>>>(
        bh + OFF_HNEW, bl + OFF_HNEW, bh + OFF_F1, bl + OFF_F1,
        1024, 128, tbuf, 512, nullptr, nullptr, nullptr);

    // 13) t = tanh(tbuf) -> bf16
    f32_split_tanh<<<(131072 / 2) / 256, 256>>>(tbuf, bh + OFF_T, bl + OFF_T, 131072 / 2);

    // 14) out += t @ fc2^T          (256x4096, K=512, splitK=2)
    gemm64<EPI_ATOMIC><<<dim3(64, 2, 2), blk, GEMM_SMEM>>>(
        bh + OFF_T, bl + OFF_T, bh + OFF_F2, bl + OFF_F2,
        512, 256, out, 4096, nullptr, nullptr, nullptr);
}